// round 14
// baseline (speedup 1.0000x reference)
#include <cuda_runtime.h>
#include <cuda_bf16.h>
#include <stdint.h>
#include <math.h>

#define N_NODES_MAX 16384
#define IN_DIM 512
#define MEM_DIM 256
#define VOCAB 64
#define MAX_CH 8

// Scratch (allocation-free rule: __device__ globals)
__device__ float g_X[N_NODES_MAX * MEM_DIM];
__device__ float g_P[N_NODES_MAX * MEM_DIM];
__device__ float g_D[VOCAB * MEM_DIM];
__device__ __nv_bfloat16 g_Wh[MEM_DIM * 1024];
__device__ __nv_bfloat16 g_Wl[MEM_DIM * 1024];
__device__ __nv_bfloat16 g_Sh[N_NODES_MAX * MEM_DIM];
__device__ __nv_bfloat16 g_Sl[N_NODES_MAX * MEM_DIM];
__device__ __nv_bfloat16 g_Ih[N_NODES_MAX * IN_DIM];
__device__ __nv_bfloat16 g_Il[N_NODES_MAX * IN_DIM];
__device__ __nv_bfloat16 g_Eh[VOCAB * MEM_DIM];
__device__ __nv_bfloat16 g_El[VOCAB * MEM_DIM];

#define AROW 24              // bf16 per smem row: 16 data + 8 pad (48B)
#define NSTAGE 6             // 6 stages = 3 groups of 2 k-tiles
// per-stage byte offsets inside one stage block
#define ST_AH 0
#define ST_AL 3072           // 64*24*2
#define ST_BH 6144
#define ST_BL 12288
#define ST_BYTES 18432

__device__ __forceinline__ void ldsm4(unsigned& r0, unsigned& r1,
                                      unsigned& r2, unsigned& r3, unsigned addr) {
    asm volatile("ldmatrix.sync.aligned.m8n8.x4.shared.b16 {%0,%1,%2,%3}, [%4];"
                 : "=r"(r0), "=r"(r1), "=r"(r2), "=r"(r3) : "r"(addr));
}

__device__ __forceinline__ void mma16816(float* c,
                                         unsigned a0, unsigned a1, unsigned a2, unsigned a3,
                                         unsigned b0, unsigned b1) {
    asm volatile(
        "mma.sync.aligned.m16n8k16.row.col.f32.bf16.bf16.f32 "
        "{%0,%1,%2,%3}, {%4,%5,%6,%7}, {%8,%9}, {%0,%1,%2,%3};"
        : "+f"(c[0]), "+f"(c[1]), "+f"(c[2]), "+f"(c[3])
        : "r"(a0), "r"(a1), "r"(a2), "r"(a3), "r"(b0), "r"(b1));
}

__device__ __forceinline__ void cp16(unsigned saddr, const void* gptr, unsigned src_bytes) {
    asm volatile("cp.async.cg.shared.global [%0], [%1], 16, %2;"
                 :: "r"(saddr), "l"(gptr), "r"(src_bytes));
}
__device__ __forceinline__ void cp_commit() {
    asm volatile("cp.async.commit_group;");
}
template<int N>
__device__ __forceinline__ void cp_wait() {
    asm volatile("cp.async.wait_group %0;" :: "n"(N));
}

__device__ __forceinline__ void split2(float x, float y,
                                       __nv_bfloat162& hi, __nv_bfloat162& lo) {
    __nv_bfloat16 hx = __float2bfloat16(x);
    __nv_bfloat16 hy = __float2bfloat16(y);
    hi = __halves2bfloat162(hx, hy);
    lo = __halves2bfloat162(__float2bfloat16(x - __bfloat162float(hx)),
                            __float2bfloat16(y - __bfloat162float(hy)));
}

// generic fp32 -> bf16 hi/lo split, 4 elems per thread
__global__ __launch_bounds__(256)
void split_f32(const float* __restrict__ src,
               __nv_bfloat16* __restrict__ h, __nv_bfloat16* __restrict__ l, int n4) {
    int i = blockIdx.x * 256 + threadIdx.x;
    if (i >= n4) return;
    float4 v = *(const float4*)(src + (long)i * 4);
    __nv_bfloat162 a, b;
    split2(v.x, v.y, a, b);
    ((__nv_bfloat162*)(h + (long)i * 4))[0] = a;
    ((__nv_bfloat162*)(l + (long)i * 4))[0] = b;
    split2(v.z, v.w, a, b);
    ((__nv_bfloat162*)(h + (long)i * 4))[1] = a;
    ((__nv_bfloat162*)(l + (long)i * 4))[1] = b;
}

// ---------------------------------------------------------------------------
// C[m,n] = sum_k A[m,k] * W[n, wofs+k] (+ bias[n]); A,W pre-split bf16 hi/lo.
// 3-pass split-bf16 tensor GEMM. 6-stage cp.async ring; each iteration
// consumes a GROUP of 2 k-tiles with ONE wait + ONE sync (half the barrier
// overhead per MMA vs the per-tile pipeline).
// Block 64(M) x 128(N), BK=16, 8 warps (2M x 4N), warp tile 32x32, 2 CTAs/SM.
// ---------------------------------------------------------------------------
template<bool HAS_BIAS, bool LEAF_TANH>
__global__ __launch_bounds__(256, 2)
void rcnn_gemm_mma(const __nv_bfloat16* __restrict__ Agh,
                   const __nv_bfloat16* __restrict__ Agl, int lda,
                   const __nv_bfloat16* __restrict__ Wh,
                   const __nv_bfloat16* __restrict__ Wl, int wofs,
                   const float* __restrict__ bias,
                   float* __restrict__ Cmat, int M, int K,
                   float* __restrict__ S,
                   __nv_bfloat16* __restrict__ Sh,
                   __nv_bfloat16* __restrict__ Sl, int first_leaf) {
    extern __shared__ char smem[];

    const int tid  = threadIdx.x;
    const int lane = tid & 31;
    const int warp = tid >> 5;
    const int wm   = warp >> 2;
    const int wn   = warp & 3;
    const int bm   = blockIdx.x * 64;
    const int bn   = blockIdx.y * 128;

    const int a_r = (tid & 127) >> 1;
    const int a_c = (tid & 1) * 8;
    const bool a_lo = (tid >= 128);
    const int b_r = tid >> 1;
    const int b_c = (tid & 1) * 8;

    const int a_gr = bm + a_r;
    const unsigned a_sz = (a_gr < M) ? 16u : 0u;
    const long a_base = (long)((a_gr < M) ? a_gr : (M - 1)) * lda;
    const __nv_bfloat16* Asrc = a_lo ? Agl : Agh;
    const long b_base = (long)(bn + b_r) * 1024 + wofs;

    unsigned smem_u = (unsigned)__cvta_generic_to_shared(smem);
    unsigned sa_t[NSTAGE], sbh_t[NSTAGE], sbl_t[NSTAGE];
    #pragma unroll
    for (int s = 0; s < NSTAGE; ++s) {
        unsigned base = smem_u + s * ST_BYTES;
        sa_t[s]  = base + (a_lo ? ST_AL : ST_AH) + (unsigned)(a_r * AROW + a_c) * 2u;
        sbh_t[s] = base + ST_BH + (unsigned)(b_r * AROW + b_c) * 2u;
        sbl_t[s] = base + ST_BL + (unsigned)(b_r * AROW + b_c) * 2u;
    }

    const int ntile  = K >> 4;    // k-tiles of 16 (always even here)
    const int ngroup = ntile >> 1;

    auto issue = [&](int t) {     // one k-tile into stage t % NSTAGE
        const int s = t % NSTAGE;
        const int kof = t * 16;
        cp16(sa_t[s],  Asrc + a_base + kof + a_c, a_sz);
        cp16(sbh_t[s], Wh + b_base + kof + b_c, 16u);
        cp16(sbl_t[s], Wl + b_base + kof + b_c, 16u);
    };

    float acc[2][4][4];
    #pragma unroll
    for (int i = 0; i < 2; ++i) {
        #pragma unroll
        for (int j = 0; j < 4; ++j) {
            #pragma unroll
            for (int q = 0; q < 4; ++q) { acc[i][j][q] = 0.f; }
        }
    }

    // prologue: groups 0 and 1 (tiles 0..3), one commit each
    issue(0); issue(1); cp_commit();
    if (ngroup > 1) { issue(2); issue(3); }
    cp_commit();

    const int gq8 = lane >> 3;
    const int wi  = lane & 7;
    const int a_row = wm * 32 + wi + 8 * (gq8 & 1);
    const int a_kh  = (gq8 >> 1) * 8;
    const int b_row = wn * 32 + wi + 8 * (gq8 >> 1);
    const int b_kh  = (gq8 & 1) * 8;
    const unsigned a_off = (unsigned)(a_row * AROW + a_kh) * 2u;
    const unsigned a_off16 = (unsigned)((a_row + 16) * AROW + a_kh) * 2u;
    const unsigned b_off = (unsigned)(b_row * AROW + b_kh) * 2u;
    const unsigned b_off16 = (unsigned)((b_row + 16) * AROW + b_kh) * 2u;

    for (int g = 0; g < ngroup; ++g) {
        cp_wait<1>();
        __syncthreads();

        // refill group g+2: its stages were consumed at iter g-1 (fenced above)
        if (2 * g + 4 < ntile) { issue(2 * g + 4); issue(2 * g + 5); }
        cp_commit();

        // fragments for both tiles of this group
        unsigned Ahf[2][2][4], Alf[2][2][4], Bhf[2][2][4], Blf[2][2][4];
        #pragma unroll
        for (int u = 0; u < 2; ++u) {
            const unsigned sbase = smem_u + (unsigned)((2 * g + u) % NSTAGE) * ST_BYTES;
            ldsm4(Ahf[u][0][0], Ahf[u][0][1], Ahf[u][0][2], Ahf[u][0][3], sbase + ST_AH + a_off);
            ldsm4(Ahf[u][1][0], Ahf[u][1][1], Ahf[u][1][2], Ahf[u][1][3], sbase + ST_AH + a_off16);
            ldsm4(Alf[u][0][0], Alf[u][0][1], Alf[u][0][2], Alf[u][0][3], sbase + ST_AL + a_off);
            ldsm4(Alf[u][1][0], Alf[u][1][1], Alf[u][1][2], Alf[u][1][3], sbase + ST_AL + a_off16);
            ldsm4(Bhf[u][0][0], Bhf[u][0][1], Bhf[u][0][2], Bhf[u][0][3], sbase + ST_BH + b_off);
            ldsm4(Bhf[u][1][0], Bhf[u][1][1], Bhf[u][1][2], Bhf[u][1][3], sbase + ST_BH + b_off16);
            ldsm4(Blf[u][0][0], Blf[u][0][1], Blf[u][0][2], Blf[u][0][3], sbase + ST_BL + b_off);
            ldsm4(Blf[u][1][0], Blf[u][1][1], Blf[u][1][2], Blf[u][1][3], sbase + ST_BL + b_off16);
        }

        // 48 MMAs; same-accumulator ops are >= 8 apart (de-chained)
        #pragma unroll
        for (int u = 0; u < 2; ++u) {
            #pragma unroll
            for (int mt = 0; mt < 2; ++mt)
                #pragma unroll
                for (int p = 0; p < 2; ++p)
                    #pragma unroll
                    for (int nh = 0; nh < 2; ++nh)
                        mma16816(acc[mt][p * 2 + nh],
                                 Ahf[u][mt][0], Ahf[u][mt][1], Ahf[u][mt][2], Ahf[u][mt][3],
                                 Bhf[u][p][2 * nh], Bhf[u][p][2 * nh + 1]);
            #pragma unroll
            for (int mt = 0; mt < 2; ++mt)
                #pragma unroll
                for (int p = 0; p < 2; ++p)
                    #pragma unroll
                    for (int nh = 0; nh < 2; ++nh)
                        mma16816(acc[mt][p * 2 + nh],
                                 Ahf[u][mt][0], Ahf[u][mt][1], Ahf[u][mt][2], Ahf[u][mt][3],
                                 Blf[u][p][2 * nh], Blf[u][p][2 * nh + 1]);
            #pragma unroll
            for (int mt = 0; mt < 2; ++mt)
                #pragma unroll
                for (int p = 0; p < 2; ++p)
                    #pragma unroll
                    for (int nh = 0; nh < 2; ++nh)
                        mma16816(acc[mt][p * 2 + nh],
                                 Alf[u][mt][0], Alf[u][mt][1], Alf[u][mt][2], Alf[u][mt][3],
                                 Bhf[u][p][2 * nh], Bhf[u][p][2 * nh + 1]);
        }
    }

    // epilogue
    const int gq  = lane >> 2;
    const int tig = lane & 3;
    #pragma unroll
    for (int mt = 0; mt < 2; ++mt) {
        #pragma unroll
        for (int rh = 0; rh < 2; ++rh) {
            const int row = bm + wm * 32 + mt * 16 + rh * 8 + gq;
            if (row >= M) continue;
            const bool leaf = LEAF_TANH && (row >= first_leaf);
            #pragma unroll
            for (int nt = 0; nt < 4; ++nt) {
                const int col = bn + wn * 32 + nt * 8 + 2 * tig;
                float v0 = acc[mt][nt][2 * rh + 0];
                float v1 = acc[mt][nt][2 * rh + 1];
                if (HAS_BIAS) { v0 += bias[col]; v1 += bias[col + 1]; }
                if (leaf) {
                    v0 = tanhf(v0); v1 = tanhf(v1);
                    *(float2*)(S + (long)row * MEM_DIM + col) = make_float2(v0, v1);
                    __nv_bfloat162 h, l;
                    split2(v0, v1, h, l);
                    *(__nv_bfloat162*)(Sh + (long)row * MEM_DIM + col) = h;
                    *(__nv_bfloat162*)(Sl + (long)row * MEM_DIM + col) = l;
                } else {
                    *(float2*)(Cmat + (long)row * MEM_DIM + col) = make_float2(v0, v1);
                }
            }
        }
    }
}

// ---------------------------------------------------------------------------
// Combine (warp-per-child for C==8; generic fallback). Writes fp32 states and
// bf16 split copies (A operand for upper-level P-GEMMs).
// ---------------------------------------------------------------------------
__global__ __launch_bounds__(256)
void rcnn_combine(int lo,
                  const int*   __restrict__ cidx,
                  const int*   __restrict__ cdep,
                  const int*   __restrict__ counts,
                  const float* __restrict__ X,
                  const float* __restrict__ D,
                  const float* __restrict__ P,
                  float*       __restrict__ S,
                  __nv_bfloat16* __restrict__ Sh,
                  __nv_bfloat16* __restrict__ Sl) {
    const int i   = lo + (int)blockIdx.x;
    const int tid = threadIdx.x;
    const int cnt = counts[i];

    __shared__ float r[MAX_CH * MEM_DIM];

    if (cnt == 8) {
        const int w = tid >> 5;
        const int l = tid & 31;
        const int g = l * 8;

        const int c  = cidx[i * MAX_CH + w];
        const int dv = cdep[i * MAX_CH + w];

        const float4 x0 = *(const float4*)(X + (long)i  * MEM_DIM + g);
        const float4 x1 = *(const float4*)(X + (long)i  * MEM_DIM + g + 4);
        const float4 d0 = *(const float4*)(D + (long)dv * MEM_DIM + g);
        const float4 d1 = *(const float4*)(D + (long)dv * MEM_DIM + g + 4);
        const float4 p0 = *(const float4*)(P + (long)c  * MEM_DIM + g);
        const float4 p1 = *(const float4*)(P + (long)c  * MEM_DIM + g + 4);

        float m = tanhf(x0.x + d0.x + p0.x);
        m = fmaxf(m, tanhf(x0.y + d0.y + p0.y));
        m = fmaxf(m, tanhf(x0.z + d0.z + p0.z));
        m = fmaxf(m, tanhf(x0.w + d0.w + p0.w));
        m = fmaxf(m, tanhf(x1.x + d1.x + p1.x));
        m = fmaxf(m, tanhf(x1.y + d1.y + p1.y));
        m = fmaxf(m, tanhf(x1.z + d1.z + p1.z));
        m = fmaxf(m, tanhf(x1.w + d1.w + p1.w));

        const long o = (long)i * MEM_DIM + w * 32 + l;
        S[o] = m;
        __nv_bfloat16 h = __float2bfloat16(m);
        Sh[o] = h;
        Sl[o] = __float2bfloat16(m - __bfloat162float(h));
        return;
    }

    const int f = tid;
    const float x = X[(long)i * MEM_DIM + f];
    const long o = (long)i * MEM_DIM + f;

    if (cnt == 0) {
        float v = tanhf(x);
        S[o] = v;
        __nv_bfloat16 h = __float2bfloat16(v);
        Sh[o] = h;
        Sl[o] = __float2bfloat16(v - __bfloat162float(h));
        return;
    }
    const int C = cnt;

    for (int k = 0; k < C; ++k) {
        int c  = cidx[i * MAX_CH + k];
        int dv = cdep[i * MAX_CH + k];
        r[k * MEM_DIM + f] = tanhf(x + D[dv * MEM_DIM + f] + P[(long)c * MEM_DIM + f]);
    }
    __syncthreads();

    float mx = -3.402823466e38f;
    for (int t = 0; t < C; ++t) {
        int j = f * C + t;
        mx = fmaxf(mx, r[(j >> 8) * MEM_DIM + (j & 255)]);
    }
    S[o] = mx;
    __nv_bfloat16 h = __float2bfloat16(mx);
    Sh[o] = h;
    Sl[o] = __float2bfloat16(mx - __bfloat162float(h));
}

// ---------------------------------------------------------------------------
extern "C" void kernel_launch(void* const* d_in, const int* in_sizes, int n_in,
                              void* d_out, int out_size) {
    const float* inputs    = (const float*)d_in[0];
    const float* W         = (const float*)d_in[1];
    const float* bvec      = (const float*)d_in[2];
    const float* deprel    = (const float*)d_in[3];
    const int*   child_idx = (const int*)  d_in[4];
    const int*   child_dep = (const int*)  d_in[5];
    const int*   counts    = (const int*)  d_in[6];
    float*       states    = (float*)d_out;

    float *X = 0, *P = 0, *D = 0;
    __nv_bfloat16 *Wh = 0, *Wl = 0, *Sh = 0, *Sl = 0, *Ih = 0, *Il = 0, *Eh = 0, *El = 0;
    cudaGetSymbolAddress((void**)&X,  g_X);
    cudaGetSymbolAddress((void**)&P,  g_P);
    cudaGetSymbolAddress((void**)&D,  g_D);
    cudaGetSymbolAddress((void**)&Wh, g_Wh);
    cudaGetSymbolAddress((void**)&Wl, g_Wl);
    cudaGetSymbolAddress((void**)&Sh, g_Sh);
    cudaGetSymbolAddress((void**)&Sl, g_Sl);
    cudaGetSymbolAddress((void**)&Ih, g_Ih);
    cudaGetSymbolAddress((void**)&Il, g_Il);
    cudaGetSymbolAddress((void**)&Eh, g_Eh);
    cudaGetSymbolAddress((void**)&El, g_El);

    const int N = in_sizes[0] / IN_DIM;               // 16384
    const int first_leaf = (N + MAX_CH - 2) / MAX_CH; // 2048
    const int SMEM = NSTAGE * ST_BYTES;               // 110592 B

    static bool attr_done = false;
    if (!attr_done) {
        cudaFuncSetAttribute(rcnn_gemm_mma<true, true>,
                             cudaFuncAttributeMaxDynamicSharedMemorySize, SMEM);
        cudaFuncSetAttribute(rcnn_gemm_mma<false, false>,
                             cudaFuncAttributeMaxDynamicSharedMemorySize, SMEM);
        attr_done = true;
    }

    // Phase -1: split all fp32 operands into bf16 hi/lo once.
    split_f32<<<(MEM_DIM * 1024 / 4 + 255) / 256, 256>>>(W, Wh, Wl, MEM_DIM * 1024 / 4);
    split_f32<<<((N * IN_DIM / 4) + 255) / 256, 256>>>(inputs, Ih, Il, N * IN_DIM / 4);
    split_f32<<<(VOCAB * MEM_DIM / 4 + 255) / 256, 256>>>(deprel, Eh, El, VOCAB * MEM_DIM / 4);

    // Phase 0: input projection + bias; leaf rows tanh'd + split in epilogue.
    rcnn_gemm_mma<true, true><<<dim3((unsigned)((N + 63) / 64), 2), 256, SMEM>>>(
        Ih, Il, IN_DIM, Wh, Wl, 0, bvec, X, N, IN_DIM, states, Sh, Sl, first_leaf);
    // deprel projection (tiny)
    rcnn_gemm_mma<false, false><<<dim3(1, 2), 256, SMEM>>>(
        Eh, El, MEM_DIM, Wh, Wl, IN_DIM, 0, D, VOCAB, MEM_DIM, 0, 0, 0, 0);

    // Level starts: s[L] = (8^L - 1)/7
    long s[12];
    s[0] = 0;
    int nl = 0;
    while (s[nl] < N) { s[nl + 1] = 8 * s[nl] + 1; nl++; }

    for (int L = nl - 1; L >= 0; --L) {
        long lo = s[L];
        long hi = s[L + 1] - 1;
        if (hi > first_leaf - 1) hi = first_leaf - 1;
        if (lo > hi) continue;

        long clo = 8 * lo + 1;
        long chi = 8 * hi + 8;
        if (chi > N - 1) chi = N - 1;
        int Mc = (int)(chi - clo + 1);

        rcnn_gemm_mma<false, false><<<dim3((unsigned)((Mc + 63) / 64), 2), 256, SMEM>>>(
            Sh + clo * MEM_DIM, Sl + clo * MEM_DIM, MEM_DIM,
            Wh, Wl, IN_DIM + MEM_DIM, 0, P + clo * MEM_DIM, Mc, MEM_DIM, 0, 0, 0, 0);

        rcnn_combine<<<(unsigned)(hi - lo + 1), 256>>>(
            (int)lo, child_idx, child_dep, counts, X, D, P, states, Sh, Sl);
    }
}

// round 15
// speedup vs baseline: 1.0196x; 1.0196x over previous
#include <cuda_runtime.h>
#include <cuda_bf16.h>
#include <stdint.h>
#include <math.h>

#define N_NODES_MAX 16384
#define IN_DIM 512
#define MEM_DIM 256
#define VOCAB 64
#define MAX_CH 8

// Scratch (allocation-free rule: __device__ globals)
__device__ float g_X[N_NODES_MAX * MEM_DIM];
__device__ float g_P[N_NODES_MAX * MEM_DIM];
__device__ float g_D[VOCAB * MEM_DIM];
__device__ __nv_bfloat16 g_Wh[MEM_DIM * 1024];
__device__ __nv_bfloat16 g_Wl[MEM_DIM * 1024];
__device__ __nv_bfloat16 g_Sh[N_NODES_MAX * MEM_DIM];
__device__ __nv_bfloat16 g_Sl[N_NODES_MAX * MEM_DIM];
__device__ __nv_bfloat16 g_Ih[N_NODES_MAX * IN_DIM];
__device__ __nv_bfloat16 g_Il[N_NODES_MAX * IN_DIM];
__device__ __nv_bfloat16 g_Eh[VOCAB * MEM_DIM];
__device__ __nv_bfloat16 g_El[VOCAB * MEM_DIM];

#define AROW 24              // bf16 per smem row: 16 data + 8 pad (48B)
#define NSTAGE 6             // 6 stages = 3 groups of 2 k-tiles
// per-stage byte offsets inside one stage block
#define ST_AH 0
#define ST_AL 3072           // 64*24*2
#define ST_BH 6144
#define ST_BL 12288
#define ST_BYTES 18432

__device__ __forceinline__ void ldsm4(unsigned& r0, unsigned& r1,
                                      unsigned& r2, unsigned& r3, unsigned addr) {
    asm volatile("ldmatrix.sync.aligned.m8n8.x4.shared.b16 {%0,%1,%2,%3}, [%4];"
                 : "=r"(r0), "=r"(r1), "=r"(r2), "=r"(r3) : "r"(addr));
}

__device__ __forceinline__ void mma16816(float* c,
                                         unsigned a0, unsigned a1, unsigned a2, unsigned a3,
                                         unsigned b0, unsigned b1) {
    asm volatile(
        "mma.sync.aligned.m16n8k16.row.col.f32.bf16.bf16.f32 "
        "{%0,%1,%2,%3}, {%4,%5,%6,%7}, {%8,%9}, {%0,%1,%2,%3};"
        : "+f"(c[0]), "+f"(c[1]), "+f"(c[2]), "+f"(c[3])
        : "r"(a0), "r"(a1), "r"(a2), "r"(a3), "r"(b0), "r"(b1));
}

__device__ __forceinline__ void cp16(unsigned saddr, const void* gptr, unsigned src_bytes) {
    asm volatile("cp.async.cg.shared.global [%0], [%1], 16, %2;"
                 :: "r"(saddr), "l"(gptr), "r"(src_bytes));
}
__device__ __forceinline__ void cp_commit() {
    asm volatile("cp.async.commit_group;");
}
template<int N>
__device__ __forceinline__ void cp_wait() {
    asm volatile("cp.async.wait_group %0;" :: "n"(N));
}

__device__ __forceinline__ void split2(float x, float y,
                                       __nv_bfloat162& hi, __nv_bfloat162& lo) {
    __nv_bfloat16 hx = __float2bfloat16(x);
    __nv_bfloat16 hy = __float2bfloat16(y);
    hi = __halves2bfloat162(hx, hy);
    lo = __halves2bfloat162(__float2bfloat16(x - __bfloat162float(hx)),
                            __float2bfloat16(y - __bfloat162float(hy)));
}

// generic fp32 -> bf16 hi/lo split, 4 elems per thread
__global__ __launch_bounds__(256)
void split_f32(const float* __restrict__ src,
               __nv_bfloat16* __restrict__ h, __nv_bfloat16* __restrict__ l, int n4) {
    int i = blockIdx.x * 256 + threadIdx.x;
    if (i >= n4) return;
    float4 v = *(const float4*)(src + (long)i * 4);
    __nv_bfloat162 a, b;
    split2(v.x, v.y, a, b);
    ((__nv_bfloat162*)(h + (long)i * 4))[0] = a;
    ((__nv_bfloat162*)(l + (long)i * 4))[0] = b;
    split2(v.z, v.w, a, b);
    ((__nv_bfloat162*)(h + (long)i * 4))[1] = a;
    ((__nv_bfloat162*)(l + (long)i * 4))[1] = b;
}

// ---------------------------------------------------------------------------
// C[m,n] = sum_k A[m,k] * W[n, wofs+k] (+ bias[n]); A,W pre-split bf16 hi/lo.
// 3-pass split-bf16 tensor GEMM. 6-stage cp.async ring; each iteration
// consumes a GROUP of 2 k-tiles with ONE wait + ONE sync (half the barrier
// overhead per MMA vs the per-tile pipeline).
// Block 64(M) x 128(N), BK=16, 8 warps (2M x 4N), warp tile 32x32, 2 CTAs/SM.
// ---------------------------------------------------------------------------
template<bool HAS_BIAS, bool LEAF_TANH>
__global__ __launch_bounds__(256, 2)
void rcnn_gemm_mma(const __nv_bfloat16* __restrict__ Agh,
                   const __nv_bfloat16* __restrict__ Agl, int lda,
                   const __nv_bfloat16* __restrict__ Wh,
                   const __nv_bfloat16* __restrict__ Wl, int wofs,
                   const float* __restrict__ bias,
                   float* __restrict__ Cmat, int M, int K,
                   float* __restrict__ S,
                   __nv_bfloat16* __restrict__ Sh,
                   __nv_bfloat16* __restrict__ Sl, int first_leaf) {
    extern __shared__ char smem[];

    const int tid  = threadIdx.x;
    const int lane = tid & 31;
    const int warp = tid >> 5;
    const int wm   = warp >> 2;
    const int wn   = warp & 3;
    const int bm   = blockIdx.x * 64;
    const int bn   = blockIdx.y * 128;

    const int a_r = (tid & 127) >> 1;
    const int a_c = (tid & 1) * 8;
    const bool a_lo = (tid >= 128);
    const int b_r = tid >> 1;
    const int b_c = (tid & 1) * 8;

    const int a_gr = bm + a_r;
    const unsigned a_sz = (a_gr < M) ? 16u : 0u;
    const long a_base = (long)((a_gr < M) ? a_gr : (M - 1)) * lda;
    const __nv_bfloat16* Asrc = a_lo ? Agl : Agh;
    const long b_base = (long)(bn + b_r) * 1024 + wofs;

    unsigned smem_u = (unsigned)__cvta_generic_to_shared(smem);
    unsigned sa_t[NSTAGE], sbh_t[NSTAGE], sbl_t[NSTAGE];
    #pragma unroll
    for (int s = 0; s < NSTAGE; ++s) {
        unsigned base = smem_u + s * ST_BYTES;
        sa_t[s]  = base + (a_lo ? ST_AL : ST_AH) + (unsigned)(a_r * AROW + a_c) * 2u;
        sbh_t[s] = base + ST_BH + (unsigned)(b_r * AROW + b_c) * 2u;
        sbl_t[s] = base + ST_BL + (unsigned)(b_r * AROW + b_c) * 2u;
    }

    const int ntile  = K >> 4;    // k-tiles of 16 (always even here)
    const int ngroup = ntile >> 1;

    auto issue = [&](int t) {     // one k-tile into stage t % NSTAGE
        const int s = t % NSTAGE;
        const int kof = t * 16;
        cp16(sa_t[s],  Asrc + a_base + kof + a_c, a_sz);
        cp16(sbh_t[s], Wh + b_base + kof + b_c, 16u);
        cp16(sbl_t[s], Wl + b_base + kof + b_c, 16u);
    };

    float acc[2][4][4];
    #pragma unroll
    for (int i = 0; i < 2; ++i) {
        #pragma unroll
        for (int j = 0; j < 4; ++j) {
            #pragma unroll
            for (int q = 0; q < 4; ++q) { acc[i][j][q] = 0.f; }
        }
    }

    // prologue: groups 0 and 1 (tiles 0..3), one commit each
    issue(0); issue(1); cp_commit();
    if (ngroup > 1) { issue(2); issue(3); }
    cp_commit();

    const int gq8 = lane >> 3;
    const int wi  = lane & 7;
    const int a_row = wm * 32 + wi + 8 * (gq8 & 1);
    const int a_kh  = (gq8 >> 1) * 8;
    const int b_row = wn * 32 + wi + 8 * (gq8 >> 1);
    const int b_kh  = (gq8 & 1) * 8;
    const unsigned a_off = (unsigned)(a_row * AROW + a_kh) * 2u;
    const unsigned a_off16 = (unsigned)((a_row + 16) * AROW + a_kh) * 2u;
    const unsigned b_off = (unsigned)(b_row * AROW + b_kh) * 2u;
    const unsigned b_off16 = (unsigned)((b_row + 16) * AROW + b_kh) * 2u;

    for (int g = 0; g < ngroup; ++g) {
        cp_wait<1>();
        __syncthreads();

        // refill group g+2: its stages were consumed at iter g-1 (fenced above)
        if (2 * g + 4 < ntile) { issue(2 * g + 4); issue(2 * g + 5); }
        cp_commit();

        // fragments for both tiles of this group
        unsigned Ahf[2][2][4], Alf[2][2][4], Bhf[2][2][4], Blf[2][2][4];
        #pragma unroll
        for (int u = 0; u < 2; ++u) {
            const unsigned sbase = smem_u + (unsigned)((2 * g + u) % NSTAGE) * ST_BYTES;
            ldsm4(Ahf[u][0][0], Ahf[u][0][1], Ahf[u][0][2], Ahf[u][0][3], sbase + ST_AH + a_off);
            ldsm4(Ahf[u][1][0], Ahf[u][1][1], Ahf[u][1][2], Ahf[u][1][3], sbase + ST_AH + a_off16);
            ldsm4(Alf[u][0][0], Alf[u][0][1], Alf[u][0][2], Alf[u][0][3], sbase + ST_AL + a_off);
            ldsm4(Alf[u][1][0], Alf[u][1][1], Alf[u][1][2], Alf[u][1][3], sbase + ST_AL + a_off16);
            ldsm4(Bhf[u][0][0], Bhf[u][0][1], Bhf[u][0][2], Bhf[u][0][3], sbase + ST_BH + b_off);
            ldsm4(Bhf[u][1][0], Bhf[u][1][1], Bhf[u][1][2], Bhf[u][1][3], sbase + ST_BH + b_off16);
            ldsm4(Blf[u][0][0], Blf[u][0][1], Blf[u][0][2], Blf[u][0][3], sbase + ST_BL + b_off);
            ldsm4(Blf[u][1][0], Blf[u][1][1], Blf[u][1][2], Blf[u][1][3], sbase + ST_BL + b_off16);
        }

        // 48 MMAs; same-accumulator ops are >= 8 apart (de-chained)
        #pragma unroll
        for (int u = 0; u < 2; ++u) {
            #pragma unroll
            for (int mt = 0; mt < 2; ++mt)
                #pragma unroll
                for (int p = 0; p < 2; ++p)
                    #pragma unroll
                    for (int nh = 0; nh < 2; ++nh)
                        mma16816(acc[mt][p * 2 + nh],
                                 Ahf[u][mt][0], Ahf[u][mt][1], Ahf[u][mt][2], Ahf[u][mt][3],
                                 Bhf[u][p][2 * nh], Bhf[u][p][2 * nh + 1]);
            #pragma unroll
            for (int mt = 0; mt < 2; ++mt)
                #pragma unroll
                for (int p = 0; p < 2; ++p)
                    #pragma unroll
                    for (int nh = 0; nh < 2; ++nh)
                        mma16816(acc[mt][p * 2 + nh],
                                 Ahf[u][mt][0], Ahf[u][mt][1], Ahf[u][mt][2], Ahf[u][mt][3],
                                 Blf[u][p][2 * nh], Blf[u][p][2 * nh + 1]);
            #pragma unroll
            for (int mt = 0; mt < 2; ++mt)
                #pragma unroll
                for (int p = 0; p < 2; ++p)
                    #pragma unroll
                    for (int nh = 0; nh < 2; ++nh)
                        mma16816(acc[mt][p * 2 + nh],
                                 Alf[u][mt][0], Alf[u][mt][1], Alf[u][mt][2], Alf[u][mt][3],
                                 Bhf[u][p][2 * nh], Bhf[u][p][2 * nh + 1]);
        }
    }

    // epilogue
    const int gq  = lane >> 2;
    const int tig = lane & 3;
    #pragma unroll
    for (int mt = 0; mt < 2; ++mt) {
        #pragma unroll
        for (int rh = 0; rh < 2; ++rh) {
            const int row = bm + wm * 32 + mt * 16 + rh * 8 + gq;
            if (row >= M) continue;
            const bool leaf = LEAF_TANH && (row >= first_leaf);
            #pragma unroll
            for (int nt = 0; nt < 4; ++nt) {
                const int col = bn + wn * 32 + nt * 8 + 2 * tig;
                float v0 = acc[mt][nt][2 * rh + 0];
                float v1 = acc[mt][nt][2 * rh + 1];
                if (HAS_BIAS) { v0 += bias[col]; v1 += bias[col + 1]; }
                if (leaf) {
                    v0 = tanhf(v0); v1 = tanhf(v1);
                    *(float2*)(S + (long)row * MEM_DIM + col) = make_float2(v0, v1);
                    __nv_bfloat162 h, l;
                    split2(v0, v1, h, l);
                    *(__nv_bfloat162*)(Sh + (long)row * MEM_DIM + col) = h;
                    *(__nv_bfloat162*)(Sl + (long)row * MEM_DIM + col) = l;
                } else {
                    *(float2*)(Cmat + (long)row * MEM_DIM + col) = make_float2(v0, v1);
                }
            }
        }
    }
}

// ---------------------------------------------------------------------------
// Combine (warp-per-child for C==8; generic fallback). Writes fp32 states and
// bf16 split copies (A operand for upper-level P-GEMMs).
// ---------------------------------------------------------------------------
__global__ __launch_bounds__(256)
void rcnn_combine(int lo,
                  const int*   __restrict__ cidx,
                  const int*   __restrict__ cdep,
                  const int*   __restrict__ counts,
                  const float* __restrict__ X,
                  const float* __restrict__ D,
                  const float* __restrict__ P,
                  float*       __restrict__ S,
                  __nv_bfloat16* __restrict__ Sh,
                  __nv_bfloat16* __restrict__ Sl) {
    const int i   = lo + (int)blockIdx.x;
    const int tid = threadIdx.x;
    const int cnt = counts[i];

    __shared__ float r[MAX_CH * MEM_DIM];

    if (cnt == 8) {
        const int w = tid >> 5;
        const int l = tid & 31;
        const int g = l * 8;

        const int c  = cidx[i * MAX_CH + w];
        const int dv = cdep[i * MAX_CH + w];

        const float4 x0 = *(const float4*)(X + (long)i  * MEM_DIM + g);
        const float4 x1 = *(const float4*)(X + (long)i  * MEM_DIM + g + 4);
        const float4 d0 = *(const float4*)(D + (long)dv * MEM_DIM + g);
        const float4 d1 = *(const float4*)(D + (long)dv * MEM_DIM + g + 4);
        const float4 p0 = *(const float4*)(P + (long)c  * MEM_DIM + g);
        const float4 p1 = *(const float4*)(P + (long)c  * MEM_DIM + g + 4);

        float m = tanhf(x0.x + d0.x + p0.x);
        m = fmaxf(m, tanhf(x0.y + d0.y + p0.y));
        m = fmaxf(m, tanhf(x0.z + d0.z + p0.z));
        m = fmaxf(m, tanhf(x0.w + d0.w + p0.w));
        m = fmaxf(m, tanhf(x1.x + d1.x + p1.x));
        m = fmaxf(m, tanhf(x1.y + d1.y + p1.y));
        m = fmaxf(m, tanhf(x1.z + d1.z + p1.z));
        m = fmaxf(m, tanhf(x1.w + d1.w + p1.w));

        const long o = (long)i * MEM_DIM + w * 32 + l;
        S[o] = m;
        __nv_bfloat16 h = __float2bfloat16(m);
        Sh[o] = h;
        Sl[o] = __float2bfloat16(m - __bfloat162float(h));
        return;
    }

    const int f = tid;
    const float x = X[(long)i * MEM_DIM + f];
    const long o = (long)i * MEM_DIM + f;

    if (cnt == 0) {
        float v = tanhf(x);
        S[o] = v;
        __nv_bfloat16 h = __float2bfloat16(v);
        Sh[o] = h;
        Sl[o] = __float2bfloat16(v - __bfloat162float(h));
        return;
    }
    const int C = cnt;

    for (int k = 0; k < C; ++k) {
        int c  = cidx[i * MAX_CH + k];
        int dv = cdep[i * MAX_CH + k];
        r[k * MEM_DIM + f] = tanhf(x + D[dv * MEM_DIM + f] + P[(long)c * MEM_DIM + f]);
    }
    __syncthreads();

    float mx = -3.402823466e38f;
    for (int t = 0; t < C; ++t) {
        int j = f * C + t;
        mx = fmaxf(mx, r[(j >> 8) * MEM_DIM + (j & 255)]);
    }
    S[o] = mx;
    __nv_bfloat16 h = __float2bfloat16(mx);
    Sh[o] = h;
    Sl[o] = __float2bfloat16(mx - __bfloat162float(h));
}

// ---------------------------------------------------------------------------
extern "C" void kernel_launch(void* const* d_in, const int* in_sizes, int n_in,
                              void* d_out, int out_size) {
    const float* inputs    = (const float*)d_in[0];
    const float* W         = (const float*)d_in[1];
    const float* bvec      = (const float*)d_in[2];
    const float* deprel    = (const float*)d_in[3];
    const int*   child_idx = (const int*)  d_in[4];
    const int*   child_dep = (const int*)  d_in[5];
    const int*   counts    = (const int*)  d_in[6];
    float*       states    = (float*)d_out;

    float *X = 0, *P = 0, *D = 0;
    __nv_bfloat16 *Wh = 0, *Wl = 0, *Sh = 0, *Sl = 0, *Ih = 0, *Il = 0, *Eh = 0, *El = 0;
    cudaGetSymbolAddress((void**)&X,  g_X);
    cudaGetSymbolAddress((void**)&P,  g_P);
    cudaGetSymbolAddress((void**)&D,  g_D);
    cudaGetSymbolAddress((void**)&Wh, g_Wh);
    cudaGetSymbolAddress((void**)&Wl, g_Wl);
    cudaGetSymbolAddress((void**)&Sh, g_Sh);
    cudaGetSymbolAddress((void**)&Sl, g_Sl);
    cudaGetSymbolAddress((void**)&Ih, g_Ih);
    cudaGetSymbolAddress((void**)&Il, g_Il);
    cudaGetSymbolAddress((void**)&Eh, g_Eh);
    cudaGetSymbolAddress((void**)&El, g_El);

    const int N = in_sizes[0] / IN_DIM;               // 16384
    const int first_leaf = (N + MAX_CH - 2) / MAX_CH; // 2048
    const int SMEM = NSTAGE * ST_BYTES;               // 110592 B

    static bool attr_done = false;
    if (!attr_done) {
        cudaFuncSetAttribute(rcnn_gemm_mma<true, true>,
                             cudaFuncAttributeMaxDynamicSharedMemorySize, SMEM);
        cudaFuncSetAttribute(rcnn_gemm_mma<false, false>,
                             cudaFuncAttributeMaxDynamicSharedMemorySize, SMEM);
        attr_done = true;
    }

    // Phase -1: split all fp32 operands into bf16 hi/lo once.
    split_f32<<<(MEM_DIM * 1024 / 4 + 255) / 256, 256>>>(W, Wh, Wl, MEM_DIM * 1024 / 4);
    split_f32<<<((N * IN_DIM / 4) + 255) / 256, 256>>>(inputs, Ih, Il, N * IN_DIM / 4);
    split_f32<<<(VOCAB * MEM_DIM / 4 + 255) / 256, 256>>>(deprel, Eh, El, VOCAB * MEM_DIM / 4);

    // Phase 0: input projection + bias; leaf rows tanh'd + split in epilogue.
    rcnn_gemm_mma<true, true><<<dim3((unsigned)((N + 63) / 64), 2), 256, SMEM>>>(
        Ih, Il, IN_DIM, Wh, Wl, 0, bvec, X, N, IN_DIM, states, Sh, Sl, first_leaf);
    // deprel projection (tiny)
    rcnn_gemm_mma<false, false><<<dim3(1, 2), 256, SMEM>>>(
        Eh, El, MEM_DIM, Wh, Wl, IN_DIM, 0, D, VOCAB, MEM_DIM, 0, 0, 0, 0);

    // Level starts: s[L] = (8^L - 1)/7
    long s[12];
    s[0] = 0;
    int nl = 0;
    while (s[nl] < N) { s[nl + 1] = 8 * s[nl] + 1; nl++; }

    for (int L = nl - 1; L >= 0; --L) {
        long lo = s[L];
        long hi = s[L + 1] - 1;
        if (hi > first_leaf - 1) hi = first_leaf - 1;
        if (lo > hi) continue;

        long clo = 8 * lo + 1;
        long chi = 8 * hi + 8;
        if (chi > N - 1) chi = N - 1;
        int Mc = (int)(chi - clo + 1);

        rcnn_gemm_mma<false, false><<<dim3((unsigned)((Mc + 63) / 64), 2), 256, SMEM>>>(
            Sh + clo * MEM_DIM, Sl + clo * MEM_DIM, MEM_DIM,
            Wh, Wl, IN_DIM + MEM_DIM, 0, P + clo * MEM_DIM, Mc, MEM_DIM, 0, 0, 0, 0);

        rcnn_combine<<<(unsigned)(hi - lo + 1), 256>>>(
            (int)lo, child_idx, child_dep, counts, X, D, P, states, Sh, Sl);
    }
}